// round 1
// baseline (speedup 1.0000x reference)
#include <cuda_runtime.h>
#include <cstdint>
#include <cstddef>

// ---------------- problem constants (fixed by the dataset) ----------------
#define NN   16384      // nodes
#define NE   262144     // static edges (== NN * 16, also dynamic edge count)
#define DD   128        // node dim
#define DE   64         // edge dim
#define HH   256        // hidden
#define KK   16         // kNN

// ---------------- device scratch (allocation-free rule: __device__ globals) ----
__device__ float g_msg [(size_t)NE * 256];           // 268 MB  (edge MLP input, 192 or 256 wide)
__device__ float g_hid [(size_t)NE * 256];           // 268 MB  (edge MLP hidden)
__device__ float g_m   [(size_t)NE * 128];           // 134 MB  (edge messages)
__device__ float g_ea0 [(size_t)NE * DE];            // 64 MB
__device__ float g_ea1 [(size_t)NE * DE];            // 64 MB
__device__ float g_xs0 [NN * DD];
__device__ float g_xs1 [NN * DD];
__device__ float g_xd0 [NN * DD];
__device__ float g_xd1 [NN * DD];
__device__ float g_agg [NN * DD];
__device__ float g_tmpN[NN * HH];
__device__ float g_cat [NN * 2 * DD];
__device__ float g_sq  [NN];
__device__ float g_xT  [(size_t)DD * NN];            // 8 MB (x transposed for dist GEMM)
__device__ float g_dist[(size_t)NN * NN];            // 1 GB distance scratch
__device__ int   g_knn [NN * KK];
__device__ int   g_ei64flag;

// ---------------- edge_index dtype handling (int64 vs silently-int32) -----
__global__ void detect_ei_k(const void* p) {
    const unsigned long long* q = (const unsigned long long*)p;
    int ok = 1;
    #pragma unroll
    for (int i = 0; i < 8; i++)
        if (q[i] >= (unsigned long long)NN) ok = 0;
    g_ei64flag = ok;
}

__device__ __forceinline__ long long load_ei(const void* p, long long idx) {
    if (g_ei64flag) return ((const long long*)p)[idx];
    return (long long)((const int*)p)[idx];
}

// ---------------- generic tiled SGEMM: C = epi(A[MxK] @ B[KxN] (+bias)) ----
// All M multiples of 128, N multiples of 64, K multiples of 32 (guaranteed by shapes).
// mode 0: relu(acc + bias[col]);  mode 1: knn epilogue: bias[col] - 2*acc
#define GBM 128
#define GBN 64
#define GBK 32

__global__ __launch_bounds__(256, 2) void gemm_k(
    const float* __restrict__ A, const float* __restrict__ B,
    const float* __restrict__ bias, float* __restrict__ C,
    int M, int K, int N, int mode)
{
    __shared__ float As[GBK][GBM + 4];
    __shared__ float Bs[GBK][GBN];
    const int tid  = threadIdx.x;
    const int row0 = blockIdx.y * GBM;
    const int col0 = blockIdx.x * GBN;
    const int tr = tid >> 4;   // 0..15 (8 rows each)
    const int tc = tid & 15;   // 0..15 (4 cols each)

    float acc[8][4];
    #pragma unroll
    for (int i = 0; i < 8; i++)
        #pragma unroll
        for (int j = 0; j < 4; j++) acc[i][j] = 0.f;

    const int ktiles = K / GBK;
    for (int kt = 0; kt < ktiles; kt++) {
        #pragma unroll
        for (int p = 0; p < 4; p++) {
            int lin = tid + 256 * p;
            int r = lin >> 3, q = lin & 7;
            const float4 v = *(const float4*)(A + (size_t)(row0 + r) * K + kt * GBK + q * 4);
            As[q * 4 + 0][r] = v.x; As[q * 4 + 1][r] = v.y;
            As[q * 4 + 2][r] = v.z; As[q * 4 + 3][r] = v.w;
        }
        #pragma unroll
        for (int p = 0; p < 2; p++) {
            int lin = tid + 256 * p;
            int kr = lin >> 4, j4 = lin & 15;
            *(float4*)&Bs[kr][j4 * 4] =
                *(const float4*)(B + (size_t)(kt * GBK + kr) * N + col0 + j4 * 4);
        }
        __syncthreads();
        #pragma unroll
        for (int k = 0; k < GBK; k++) {
            float a[8], b[4];
            *(float4*)&a[0] = *(const float4*)&As[k][tr * 8];
            *(float4*)&a[4] = *(const float4*)&As[k][tr * 8 + 4];
            *(float4*)&b[0] = *(const float4*)&Bs[k][tc * 4];
            #pragma unroll
            for (int i = 0; i < 8; i++)
                #pragma unroll
                for (int j = 0; j < 4; j++)
                    acc[i][j] = fmaf(a[i], b[j], acc[i][j]);
        }
        __syncthreads();
    }

    float bv[4];
    #pragma unroll
    for (int j = 0; j < 4; j++) bv[j] = bias[col0 + tc * 4 + j];

    #pragma unroll
    for (int i = 0; i < 8; i++) {
        const int row = row0 + tr * 8 + i;
        float4 o;
        if (mode == 0) {
            o.x = fmaxf(acc[i][0] + bv[0], 0.f);
            o.y = fmaxf(acc[i][1] + bv[1], 0.f);
            o.z = fmaxf(acc[i][2] + bv[2], 0.f);
            o.w = fmaxf(acc[i][3] + bv[3], 0.f);
        } else {
            o.x = bv[0] - 2.f * acc[i][0];
            o.y = bv[1] - 2.f * acc[i][1];
            o.z = bv[2] - 2.f * acc[i][2];
            o.w = bv[3] - 2.f * acc[i][3];
        }
        *(float4*)(C + (size_t)row * N + col0 + tc * 4) = o;
    }
}

// ---------------- small helper kernels --------------------------------------
// static message build: msg[e] = [ea[e](64) | xs[src]-xs[dst](128)]
__global__ void build_smsg_k(const float* __restrict__ ea, const float* __restrict__ xs,
                             const void* __restrict__ ei, float* __restrict__ msg)
{
    const int e = blockIdx.x, t = threadIdx.x;
    if (t < DE) {
        msg[(size_t)e * 192 + t] = ea[(size_t)e * DE + t];
    } else {
        const long long s = load_ei(ei, e);
        const long long d = load_ei(ei, (long long)NE + e);
        const int c = t - DE;
        msg[(size_t)e * 192 + t] = xs[s * DD + c] - xs[d * DD + c];
    }
}

// scatter-add of messages onto destination nodes
__global__ void scatter_add_k(float* __restrict__ agg, const float* __restrict__ m,
                              const void* __restrict__ ei)
{
    const int e = blockIdx.x, t = threadIdx.x;
    const long long d = load_ei(ei, (long long)NE + e);
    atomicAdd(&agg[d * DD + t], m[(size_t)e * DD + t]);
}

// per-row squared norms (8 rows per 256-thread block, 1 warp per row)
__global__ void rownorm_k(const float* __restrict__ x, float* __restrict__ sq)
{
    const int row  = blockIdx.x * 8 + (threadIdx.x >> 5);
    const int lane = threadIdx.x & 31;
    const float* p = x + (size_t)row * DD;
    float s = 0.f;
    #pragma unroll
    for (int q = 0; q < 4; q++) { float v = p[lane + 32 * q]; s = fmaf(v, v, s); }
    #pragma unroll
    for (int o = 16; o > 0; o >>= 1) s += __shfl_xor_sync(0xffffffffu, s, o);
    if (lane == 0) sq[row] = s;
}

// transpose NN x 128 -> 128 x NN
__global__ void transpose_k(const float* __restrict__ in, float* __restrict__ out)
{
    __shared__ float t[32][33];
    const int j0 = blockIdx.x * 32, k0 = blockIdx.y * 32;
    for (int r = threadIdx.y; r < 32; r += 8)
        t[r][threadIdx.x] = in[(size_t)(j0 + r) * DD + k0 + threadIdx.x];
    __syncthreads();
    for (int r = threadIdx.y; r < 32; r += 8)
        out[(size_t)(k0 + r) * NN + j0 + threadIdx.x] = t[threadIdx.x][r];
}

// per-row top-16 smallest of dist row (tie -> lower index), matching jax top_k(-d)
__global__ __launch_bounds__(256) void topk_k(const float* __restrict__ dist,
                                              int* __restrict__ knn)
{
    __shared__ float sd[256 * 16];
    __shared__ int   si[256 * 16];
    const int i = blockIdx.x, t = threadIdx.x;
    const float* row = dist + (size_t)i * NN;

    float ld[KK]; int li[KK];
    #pragma unroll
    for (int q = 0; q < KK; q++) { ld[q] = __int_as_float(0x7f800000); li[q] = 0x7FFFFFFF; }
    float worst = __int_as_float(0x7f800000); int worsti = 0x7FFFFFFF;

    for (int j = t; j < NN; j += 256) {
        const float r = row[j];
        if (r < worst || (r == worst && j < worsti)) {
            int p = KK - 1;
            while (p > 0) {
                const bool gt = (ld[p-1] > r) || (ld[p-1] == r && li[p-1] > j);
                if (!gt) break;
                ld[p] = ld[p-1]; li[p] = li[p-1]; p--;
            }
            ld[p] = r; li[p] = j;
            worst = ld[KK-1]; worsti = li[KK-1];
        }
    }
    #pragma unroll
    for (int q = 0; q < KK; q++) { sd[t * KK + q] = ld[q]; si[t * KK + q] = li[q]; }

    for (int s = 128; s > 0; s >>= 1) {
        __syncthreads();
        if (t < s) {
            float od[KK]; int oi[KK];
            int pa = t * KK, pb = (t + s) * KK;
            const int ea_ = pa + KK, eb_ = pb + KK;
            #pragma unroll
            for (int q = 0; q < KK; q++) {
                const float da = (pa < ea_) ? sd[pa] : __int_as_float(0x7f800000);
                const int   ia = (pa < ea_) ? si[pa] : 0x7FFFFFFF;
                const float db = (pb < eb_) ? sd[pb] : __int_as_float(0x7f800000);
                const int   ib = (pb < eb_) ? si[pb] : 0x7FFFFFFF;
                const bool ta = (da < db) || (da == db && ia < ib);
                if (ta) { od[q] = da; oi[q] = ia; pa++; }
                else    { od[q] = db; oi[q] = ib; pb++; }
            }
            #pragma unroll
            for (int q = 0; q < KK; q++) { sd[t * KK + q] = od[q]; si[t * KK + q] = oi[q]; }
        }
    }
    __syncthreads();
    if (t < KK) knn[i * KK + t] = si[t];
}

// dynamic message build: msg[e=i*16+t] = [xd[i](128) | xd[nbr]-xd[i](128)]
__global__ void build_dmsg_k(const float* __restrict__ xd, const int* __restrict__ knn,
                             float* __restrict__ msg)
{
    const int e = blockIdx.x, c = threadIdx.x;
    const int i = e >> 4;
    const int j = knn[e];
    const int cc = c & 127;
    const float xi = xd[i * DD + cc];
    const float v  = (c < DD) ? xi : (xd[j * DD + cc] - xi);
    msg[(size_t)e * 256 + c] = v;
}

// dynamic aggregation: contiguous sum of 16 message rows per node
__global__ void dyn_agg_k(const float* __restrict__ m, float* __restrict__ agg)
{
    const int i = blockIdx.x, d = threadIdx.x;
    const float* p = m + (size_t)i * KK * DD + d;
    float s = 0.f;
    #pragma unroll
    for (int t = 0; t < KK; t++) s += p[t * DD];
    agg[i * DD + d] = s;
}

__global__ void concat_k(const float* __restrict__ a, const float* __restrict__ b,
                         float* __restrict__ out)
{
    const int i = blockIdx.x, c = threadIdx.x;
    out[(size_t)i * 256 + c] = (c < DD) ? a[i * DD + c] : b[i * DD + c - DD];
}

// ---------------- host orchestration ---------------------------------------
static inline void gemm(const float* A, const float* B, const float* bias, float* C,
                        int M, int K, int N, int mode)
{
    dim3 g(N / GBN, M / GBM);
    gemm_k<<<g, 256>>>(A, B, bias, C, M, K, N, mode);
}

extern "C" void kernel_launch(void* const* d_in, const int* in_sizes, int n_in,
                              void* d_out, int out_size)
{
    const float* x    = (const float*)d_in[0];
    const float* ea_i = (const float*)d_in[1];
    const float* sW1  = (const float*)d_in[2];
    const float* sb1  = (const float*)d_in[3];
    const float* sW2  = (const float*)d_in[4];
    const float* sb2  = (const float*)d_in[5];
    const float* uW1  = (const float*)d_in[6];
    const float* ub1  = (const float*)d_in[7];
    const float* uW2  = (const float*)d_in[8];
    const float* ub2  = (const float*)d_in[9];
    const float* rW   = (const float*)d_in[10];
    const float* rb   = (const float*)d_in[11];
    const float* dW1  = (const float*)d_in[12];
    const float* db1  = (const float*)d_in[13];
    const float* dW2  = (const float*)d_in[14];
    const float* db2  = (const float*)d_in[15];
    const float* dUW1 = (const float*)d_in[16];
    const float* dUb1 = (const float*)d_in[17];
    const float* dUW2 = (const float*)d_in[18];
    const float* dUb2 = (const float*)d_in[19];
    const float* fW1  = (const float*)d_in[20];
    const float* fb1  = (const float*)d_in[21];
    const float* fW2  = (const float*)d_in[22];
    const float* fb2  = (const float*)d_in[23];
    const void*  ei   = d_in[24];
    // d_in[25] = k (constant 16, baked in)

    float *msg, *hid, *m, *ea0, *ea1, *xs0, *xs1, *xd0, *xd1;
    float *agg, *tmpN, *cat, *sq, *xT, *dist;
    int   *knn;
    cudaGetSymbolAddress((void**)&msg,  g_msg);
    cudaGetSymbolAddress((void**)&hid,  g_hid);
    cudaGetSymbolAddress((void**)&m,    g_m);
    cudaGetSymbolAddress((void**)&ea0,  g_ea0);
    cudaGetSymbolAddress((void**)&ea1,  g_ea1);
    cudaGetSymbolAddress((void**)&xs0,  g_xs0);
    cudaGetSymbolAddress((void**)&xs1,  g_xs1);
    cudaGetSymbolAddress((void**)&xd0,  g_xd0);
    cudaGetSymbolAddress((void**)&xd1,  g_xd1);
    cudaGetSymbolAddress((void**)&agg,  g_agg);
    cudaGetSymbolAddress((void**)&tmpN, g_tmpN);
    cudaGetSymbolAddress((void**)&cat,  g_cat);
    cudaGetSymbolAddress((void**)&sq,   g_sq);
    cudaGetSymbolAddress((void**)&xT,   g_xT);
    cudaGetSymbolAddress((void**)&dist, g_dist);
    cudaGetSymbolAddress((void**)&knn,  g_knn);

    detect_ei_k<<<1, 1>>>(ei);

    // ---------------- static branch: 3 conv layers + 2 edge refiners --------
    const float* xs_in = x;
    const float* ea_in = ea_i;
    float* xs_bufs[2] = { xs0, xs1 };
    float* ea_bufs[2] = { ea0, ea1 };
    for (int i = 0; i < 3; i++) {
        build_smsg_k<<<NE, 192>>>(ea_in, xs_in, ei, msg);
        gemm(msg, sW1 + (size_t)i * 192 * HH, sb1 + i * HH, hid, NE, 192, HH, 0);
        gemm(hid, sW2 + (size_t)i * HH * DD,  sb2 + i * DD, m,   NE, HH, DD, 0);
        cudaMemsetAsync(agg, 0, (size_t)NN * DD * sizeof(float));
        scatter_add_k<<<NE, DD>>>(agg, m, ei);
        gemm(agg,  uW1 + (size_t)i * DD * HH, ub1 + i * HH, tmpN, NN, DD, HH, 0);
        float* xs_out = xs_bufs[i & 1];
        gemm(tmpN, uW2 + (size_t)i * HH * DD, ub2 + i * DD, xs_out, NN, HH, DD, 0);
        if (i < 2) {
            float* ea_out = ea_bufs[i & 1];
            gemm(ea_in, rW + (size_t)i * DE * DE, rb + i * DE, ea_out, NE, DE, DE, 0);
            ea_in = ea_out;
        }
        xs_in = xs_out;
    }

    // ---------------- dynamic branch: 2 kNN conv layers ---------------------
    const float* xd_in = x;
    float* xd_bufs[2] = { xd0, xd1 };
    for (int i = 0; i < 2; i++) {
        rownorm_k<<<NN / 8, 256>>>(xd_in, sq);
        transpose_k<<<dim3(NN / 32, DD / 32), dim3(32, 8)>>>(xd_in, xT);
        // dist[i][j] = sq[j] - 2 * <xd_i, xd_j>  (row-constant +sq[i] dropped; same top-k)
        gemm(xd_in, xT, sq, dist, NN, DD, NN, 1);
        topk_k<<<NN, 256>>>(dist, knn);
        build_dmsg_k<<<NE, 256>>>(xd_in, knn, msg);
        gemm(msg, dW1 + (size_t)i * 256 * HH, db1 + i * HH, hid, NE, 256, HH, 0);
        gemm(hid, dW2 + (size_t)i * HH * DD,  db2 + i * DD, m,   NE, HH, DD, 0);
        dyn_agg_k<<<NN, DD>>>(m, agg);
        gemm(agg,  dUW1 + (size_t)i * DD * HH, dUb1 + i * HH, tmpN, NN, DD, HH, 0);
        float* xd_out = xd_bufs[i];
        gemm(tmpN, dUW2 + (size_t)i * HH * DD, dUb2 + i * DD, xd_out, NN, HH, DD, 0);
        xd_in = xd_out;
    }

    // ---------------- fuse ---------------------------------------------------
    concat_k<<<NN, 256>>>(xs_in, xd_in, cat);
    gemm(cat,  fW1, fb1, tmpN, NN, 2 * DD, HH, 0);
    gemm(tmpN, fW2, fb2, (float*)d_out, NN, HH, DD, 0);
}